// round 7
// baseline (speedup 1.0000x reference)
#include <cuda_runtime.h>
#include <cuda_bf16.h>
#include <cstdint>

#define N_NODES   50000
#define DIM 128
#define CAP 160   // bucket slots per node (Poisson(64): P(>160)~1e-24)

// Scratch (__device__ globals per allocation rules)
__device__ __align__(16) float g_agg[(size_t)N_NODES * DIM];        // agg_mean fp32
__device__ __align__(16) __nv_bfloat16 g_xb[(size_t)N_NODES * DIM]; // x in bf16
__device__ int g_cnt[N_NODES];               // cursor during fill == degree after
__device__ int g_bkt[(size_t)N_NODES * CAP]; // bucketed adjacency (both directions)
__device__ int g_is64;

// ---------------------------------------------------------------------------
// dtype probe: int64 indices < 2^31 have all-zero odd 32-bit words.
// ---------------------------------------------------------------------------
__global__ void detect_dtype_kernel(const int* __restrict__ ei32) {
    int all_zero = 1;
#pragma unroll
    for (int i = 0; i < 32; i++)
        if (ei32[2 * i + 1] != 0) all_zero = 0;
    g_is64 = all_zero;
}

// ---------------------------------------------------------------------------
// Convert x -> bf16 scratch (forked stream).
// ---------------------------------------------------------------------------
__global__ void __launch_bounds__(256)
convert_kernel(const float* __restrict__ x) {
    int i = blockIdx.x * blockDim.x + threadIdx.x;
    if (i >= N_NODES * (DIM / 4)) return;
    float4 v = reinterpret_cast<const float4*>(x)[i];
    __nv_bfloat162 lo = __float22bfloat162_rn(make_float2(v.x, v.y));
    __nv_bfloat162 hi = __float22bfloat162_rn(make_float2(v.z, v.w));
    uint2 o;
    o.x = *reinterpret_cast<uint32_t*>(&lo);
    o.y = *reinterpret_cast<uint32_t*>(&hi);
    reinterpret_cast<uint2*>(g_xb)[i] = o;
}

// ---------------------------------------------------------------------------
// Single-pass bucket fill (LSU-issue bound ~46us — at floor for structure).
// ---------------------------------------------------------------------------
__device__ __forceinline__ void insert_edge(int s, int d) {
    if ((unsigned)s >= N_NODES || (unsigned)d >= N_NODES) return;
    int ps = atomicAdd(&g_cnt[s], 1);
    if (ps < CAP) g_bkt[(size_t)s * CAP + ps] = d;
    int pd = atomicAdd(&g_cnt[d], 1);
    if (pd < CAP) g_bkt[(size_t)d * CAP + pd] = s;
}

__global__ void __launch_bounds__(256)
fill_kernel(const int* __restrict__ ei32, int n_edges) {
    int e = blockIdx.x * blockDim.x + threadIdx.x;
    if (g_is64) {
        if (e >= n_edges) return;
        int4 q = reinterpret_cast<const int4*>(ei32)[e];
        insert_edge(q.x, q.z);
    } else {
        int e0 = 2 * e;
        if (e0 >= n_edges) return;
        int4 q = reinterpret_cast<const int4*>(ei32)[e];
        insert_edge(q.x, q.y);
        if (e0 + 1 < n_edges) insert_edge(q.z, q.w);
    }
}

// ---------------------------------------------------------------------------
// Gather v4: 1 node per warp, lane owns 4 dims (uint2 = 4 bf16).
// 32-neighbor chunks: 1 coalesced index LDG, two 16-deep batches of
// __ldcg row loads (MLP=16, L1 bypass). f32x2 packed accumulation.
// ---------------------------------------------------------------------------
__device__ __forceinline__ void acc_word(uint32_t w, unsigned long long& acc) {
    uint32_t lo = w << 16;            // bf16 elem0 -> fp32 bits
    uint32_t hi = w & 0xFFFF0000u;    // bf16 elem1 -> fp32 bits
    unsigned long long p;
    asm("mov.b64 %0, {%1, %2};" : "=l"(p) : "r"(lo), "r"(hi));
    asm("add.rn.f32x2 %0, %0, %1;" : "+l"(acc) : "l"(p));
}

__device__ __forceinline__ float2 unpack_f32x2(unsigned long long v) {
    uint32_t lo, hi;
    asm("mov.b64 {%0, %1}, %2;" : "=r"(lo), "=r"(hi) : "l"(v));
    return make_float2(__uint_as_float(lo), __uint_as_float(hi));
}

__global__ void __launch_bounds__(256)
gather_kernel(int node0, int n_here) {
    int w = (blockIdx.x * blockDim.x + threadIdx.x) >> 5;
    int lane = threadIdx.x & 31;
    if (w >= n_here) return;
    int node = node0 + w;

    int deg = g_cnt[node];
    int m = (deg < CAP) ? deg : CAP;

    const uint2* __restrict__ xb  = reinterpret_cast<const uint2*>(g_xb);
    const int*   __restrict__ bkt = g_bkt + (size_t)node * CAP;

    unsigned long long a0 = 0ull, a1 = 0ull; // each holds 2 packed fp32

    int i = 0;
    for (; i + 32 <= m; i += 32) {
        int myidx = bkt[i + lane];             // 32 indices, 1 coalesced LDG
#pragma unroll
        for (int h = 0; h < 2; h++) {
            uint2 v[16];
#pragma unroll
            for (int u = 0; u < 16; u++) {     // 16 loads in flight
                int n = __shfl_sync(0xffffffffu, myidx, h * 16 + u);
                v[u] = __ldcg(&xb[(size_t)n * 32 + lane]);
            }
#pragma unroll
            for (int u = 0; u < 16; u++) {
                acc_word(v[u].x, a0);
                acc_word(v[u].y, a1);
            }
        }
    }
    // tail (< 32 neighbors)
    int rem = m - i;
    if (rem > 0) {
        int myidx = (lane < rem) ? bkt[i + lane] : 0;
        int j = 0;
        for (; j + 8 <= rem; j += 8) {
            uint2 v[8];
#pragma unroll
            for (int u = 0; u < 8; u++) {
                int n = __shfl_sync(0xffffffffu, myidx, j + u);
                v[u] = __ldcg(&xb[(size_t)n * 32 + lane]);
            }
#pragma unroll
            for (int u = 0; u < 8; u++) {
                acc_word(v[u].x, a0);
                acc_word(v[u].y, a1);
            }
        }
        for (; j < rem; j++) {
            int n = __shfl_sync(0xffffffffu, myidx, j);
            uint2 v = __ldcg(&xb[(size_t)n * 32 + lane]);
            acc_word(v.x, a0);
            acc_word(v.y, a1);
        }
    }

    float inv = 1.0f / fmaxf((float)deg, 1.0f);
    float2 f0 = unpack_f32x2(a0), f1 = unpack_f32x2(a1);
    float4 r = make_float4(f0.x * inv, f0.y * inv, f1.x * inv, f1.y * inv);
    reinterpret_cast<float4*>(g_agg)[(size_t)node * 32 + lane] = r;
}

// ---------------------------------------------------------------------------
// GEMM A (forked stream): out = x @ W_self + b.
// ---------------------------------------------------------------------------
__global__ void __launch_bounds__(128)
self_gemm_kernel(const float* __restrict__ x,
                 const float* __restrict__ W_self,
                 const float* __restrict__ b,
                 float* __restrict__ out) {
    __shared__ float xs[8][DIM];
    int row0 = blockIdx.x * 8;
    int t = threadIdx.x;

#pragma unroll
    for (int r = 0; r < 8; r++)
        xs[r][t] = x[(size_t)(row0 + r) * DIM + t];
    __syncthreads();

    float acc[8];
    float bias = b[t];
#pragma unroll
    for (int r = 0; r < 8; r++) acc[r] = bias;

    for (int k4 = 0; k4 < DIM; k4 += 4) {
        float4 av[8];
#pragma unroll
        for (int r = 0; r < 8; r++)
            av[r] = *reinterpret_cast<const float4*>(&xs[r][k4]);
#pragma unroll
        for (int kk = 0; kk < 4; kk++) {
            float ws = W_self[(k4 + kk) * DIM + t];
#pragma unroll
            for (int r = 0; r < 8; r++) {
                const float* avp = reinterpret_cast<const float*>(&av[r]);
                acc[r] = fmaf(avp[kk], ws, acc[r]);
            }
        }
    }
#pragma unroll
    for (int r = 0; r < 8; r++)
        out[(size_t)(row0 + r) * DIM + t] = acc[r];
}

// ---------------------------------------------------------------------------
// GEMM B: out[row0..] += agg_mean @ W_neigh (range-split for pipelining).
// ---------------------------------------------------------------------------
__global__ void __launch_bounds__(128)
neigh_gemm_kernel(const float* __restrict__ W_neigh,
                  float* __restrict__ out, int rowbase) {
    __shared__ float as[8][DIM];
    int row0 = rowbase + blockIdx.x * 8;
    int t = threadIdx.x;

#pragma unroll
    for (int r = 0; r < 8; r++)
        as[r][t] = g_agg[(size_t)(row0 + r) * DIM + t];
    __syncthreads();

    float acc[8] = {0.f, 0.f, 0.f, 0.f, 0.f, 0.f, 0.f, 0.f};

    for (int k4 = 0; k4 < DIM; k4 += 4) {
        float4 av[8];
#pragma unroll
        for (int r = 0; r < 8; r++)
            av[r] = *reinterpret_cast<const float4*>(&as[r][k4]);
#pragma unroll
        for (int kk = 0; kk < 4; kk++) {
            float wn = W_neigh[(k4 + kk) * DIM + t];
#pragma unroll
            for (int r = 0; r < 8; r++) {
                const float* avp = reinterpret_cast<const float*>(&av[r]);
                acc[r] = fmaf(avp[kk], wn, acc[r]);
            }
        }
    }
#pragma unroll
    for (int r = 0; r < 8; r++) {
        size_t idx = (size_t)(row0 + r) * DIM + t;
        out[idx] = out[idx] + acc[r];
    }
}

// ---------------------------------------------------------------------------
// Launch graph:
// s2:    detect -> convert -> self_gemm -> [wait g0] neigh_gemm(rows 0..N/2)
// main:  memset(cnt) -> [wait det] fill -> [wait cvt] gather(0..N/2)
//        -> gather(N/2..N) -> [wait self] neigh_gemm(N/2..N) -> [wait n0] done
// ---------------------------------------------------------------------------
extern "C" void kernel_launch(void* const* d_in, const int* in_sizes, int n_in,
                              void* d_out, int out_size) {
    const float* x    = (const float*)d_in[0];
    const int*   ei32 = (const int*)d_in[1];
    const float* Wn   = (const float*)d_in[2];
    const float* Ws   = (const float*)d_in[3];
    const float* bias = (const float*)d_in[4];
    float* out = (float*)d_out;

    int n_edges = in_sizes[1] / 2;
    const int HALF = N_NODES / 2;   // 25000

    void* cnt_ptr = nullptr;
    cudaGetSymbolAddress(&cnt_ptr, g_cnt);

    cudaStream_t s2;
    cudaStreamCreateWithFlags(&s2, cudaStreamNonBlocking);
    cudaEvent_t eFork, eDet, eCvt, eSelf, eG0, eN0;
    cudaEventCreateWithFlags(&eFork, cudaEventDisableTiming);
    cudaEventCreateWithFlags(&eDet,  cudaEventDisableTiming);
    cudaEventCreateWithFlags(&eCvt,  cudaEventDisableTiming);
    cudaEventCreateWithFlags(&eSelf, cudaEventDisableTiming);
    cudaEventCreateWithFlags(&eG0,   cudaEventDisableTiming);
    cudaEventCreateWithFlags(&eN0,   cudaEventDisableTiming);

    cudaEventRecord(eFork, 0);
    cudaStreamWaitEvent(s2, eFork, 0);

    // side stream: detect + convert + self-GEMM
    detect_dtype_kernel<<<1, 1, 0, s2>>>(ei32);
    cudaEventRecord(eDet, s2);
    int n4 = N_NODES * (DIM / 4);
    convert_kernel<<<(n4 + 255) / 256, 256, 0, s2>>>(x);
    cudaEventRecord(eCvt, s2);
    self_gemm_kernel<<<N_NODES / 8, 128, 0, s2>>>(x, Ws, bias, out);
    cudaEventRecord(eSelf, s2);

    // main: CSR fill
    cudaMemsetAsync(cnt_ptr, 0, (size_t)N_NODES * sizeof(int));
    cudaStreamWaitEvent(0, eDet, 0);
    fill_kernel<<<(n_edges + 255) / 256, 256>>>(ei32, n_edges);

    // gather first half, then second half (pipelined with neigh_gemm0 on s2)
    cudaStreamWaitEvent(0, eCvt, 0);
    gather_kernel<<<(HALF * 32) / 256, 256>>>(0, HALF);
    cudaEventRecord(eG0, 0);
    gather_kernel<<<(HALF * 32) / 256, 256>>>(HALF, HALF);

    // s2: neigh_gemm on first half (after self_gemm wrote out, gather0 done)
    cudaStreamWaitEvent(s2, eG0, 0);
    neigh_gemm_kernel<<<HALF / 8, 128, 0, s2>>>(Wn, out, 0);
    cudaEventRecord(eN0, s2);

    // main: neigh_gemm on second half, then join s2
    cudaStreamWaitEvent(0, eSelf, 0);
    neigh_gemm_kernel<<<HALF / 8, 128>>>(Wn, out, HALF);
    cudaStreamWaitEvent(0, eN0, 0);   // join fork before capture ends

    // Handles intentionally not destroyed mid-capture (host-side only).
}

// round 9
// speedup vs baseline: 1.5411x; 1.5411x over previous
#include <cuda_runtime.h>
#include <cuda_bf16.h>
#include <cstdint>

#define N_NODES 50000
#define DIM 128
#define CAP 160                        // bucket slots/node (Poisson(64): P(>160)~1e-24)
#define NTILES ((N_NODES + 127) / 128) // 391

// Scratch (__device__ globals per allocation rules)
__device__ __align__(16) float g_agg[(size_t)N_NODES * DIM];        // agg_mean fp32
__device__ __align__(16) __nv_bfloat16 g_xb[(size_t)N_NODES * DIM]; // x in bf16
__device__ int g_cnt[N_NODES];               // cursor during fill == degree after
__device__ int g_bkt[(size_t)N_NODES * CAP]; // bucketed adjacency (both directions)
__device__ __align__(16) float g_wt[128 * 256]; // WT_cat[n][k] = W*[k][n], tf32-rounded

__device__ __forceinline__ uint32_t tf32_rna(float f) {
    uint32_t r;
    asm("cvt.rna.tf32.f32 %0, %1;" : "=r"(r) : "f"(f));
    return r;
}

// ---------------------------------------------------------------------------
// Convert x -> bf16 scratch (forked stream).
// ---------------------------------------------------------------------------
__global__ void __launch_bounds__(256)
convert_kernel(const float* __restrict__ x) {
    int i = blockIdx.x * blockDim.x + threadIdx.x;
    if (i >= N_NODES * (DIM / 4)) return;
    float4 v = reinterpret_cast<const float4*>(x)[i];
    __nv_bfloat162 lo = __float22bfloat162_rn(make_float2(v.x, v.y));
    __nv_bfloat162 hi = __float22bfloat162_rn(make_float2(v.z, v.w));
    uint2 o;
    o.x = *reinterpret_cast<uint32_t*>(&lo);
    o.y = *reinterpret_cast<uint32_t*>(&hi);
    reinterpret_cast<uint2*>(g_xb)[i] = o;
}

// ---------------------------------------------------------------------------
// Build WT_cat[n][k] = (k<128 ? Wn[k][n] : Ws[k-128][n]), tf32-rounded.
// ---------------------------------------------------------------------------
__global__ void __launch_bounds__(256)
wt_kernel(const float* __restrict__ Wn, const float* __restrict__ Ws) {
    int idx = blockIdx.x * 256 + threadIdx.x;   // 32768 total
    if (idx >= 128 * 256) return;
    int k = idx >> 7;        // 0..255
    int n = idx & 127;       // coalesced read within a W row
    float v = (k < 128) ? Wn[k * 128 + n] : Ws[(k - 128) * 128 + n];
    g_wt[n * 256 + k] = __uint_as_float(tf32_rna(v));
}

// ---------------------------------------------------------------------------
// Bucket fill with inline dtype detect (int64 indices -> odd words all zero).
// ---------------------------------------------------------------------------
__device__ __forceinline__ void insert_edge(int s, int d) {
    if ((unsigned)s >= N_NODES || (unsigned)d >= N_NODES) return;
    int ps = atomicAdd(&g_cnt[s], 1);
    if (ps < CAP) g_bkt[(size_t)s * CAP + ps] = d;
    int pd = atomicAdd(&g_cnt[d], 1);
    if (pd < CAP) g_bkt[(size_t)d * CAP + pd] = s;
}

__global__ void __launch_bounds__(256)
fill_kernel(const int* __restrict__ ei32, int n_edges) {
    bool is64 = ((ei32[1] | ei32[3] | ei32[5] | ei32[7]) == 0);  // L1 broadcast
    int e = blockIdx.x * blockDim.x + threadIdx.x;
    if (is64) {
        if (e >= n_edges) return;
        int4 q = reinterpret_cast<const int4*>(ei32)[e];
        insert_edge(q.x, q.z);
    } else {
        int e0 = 2 * e;
        if (e0 >= n_edges) return;
        int4 q = reinterpret_cast<const int4*>(ei32)[e];
        insert_edge(q.x, q.y);
        if (e0 + 1 < n_edges) insert_edge(q.z, q.w);
    }
}

// ---------------------------------------------------------------------------
// Gather-sum (R5 best variant): 1 node/warp, lane owns 4 dims (uint2 bf16),
// coalesced index load + shfl, 8-deep MLP, f32x2 packed accumulation.
// ---------------------------------------------------------------------------
__device__ __forceinline__ void acc_word(uint32_t w, unsigned long long& acc) {
    uint32_t lo = w << 16;
    uint32_t hi = w & 0xFFFF0000u;
    unsigned long long p;
    asm("mov.b64 %0, {%1, %2};" : "=l"(p) : "r"(lo), "r"(hi));
    asm("add.rn.f32x2 %0, %0, %1;" : "+l"(acc) : "l"(p));
}
__device__ __forceinline__ float2 unpack_f32x2(unsigned long long v) {
    uint32_t lo, hi;
    asm("mov.b64 {%0, %1}, %2;" : "=r"(lo), "=r"(hi) : "l"(v));
    return make_float2(__uint_as_float(lo), __uint_as_float(hi));
}

__global__ void __launch_bounds__(256)
gather_kernel() {
    int node = (blockIdx.x * blockDim.x + threadIdx.x) >> 5;
    int lane = threadIdx.x & 31;
    if (node >= N_NODES) return;

    int deg = g_cnt[node];
    int m = (deg < CAP) ? deg : CAP;

    const uint2* __restrict__ xb  = reinterpret_cast<const uint2*>(g_xb);
    const int*   __restrict__ bkt = g_bkt + (size_t)node * CAP;

    unsigned long long a0 = 0ull, a1 = 0ull;

    int i = 0;
    for (; i + 32 <= m; i += 32) {
        int myidx = bkt[i + lane];
#pragma unroll
        for (int h = 0; h < 4; h++) {
            uint2 v[8];
#pragma unroll
            for (int u = 0; u < 8; u++) {
                int n = __shfl_sync(0xffffffffu, myidx, h * 8 + u);
                v[u] = xb[(size_t)n * 32 + lane];
            }
#pragma unroll
            for (int u = 0; u < 8; u++) {
                acc_word(v[u].x, a0);
                acc_word(v[u].y, a1);
            }
        }
    }
    int rem = m - i;
    if (rem > 0) {
        int myidx = (lane < rem) ? bkt[i + lane] : 0;
        int j = 0;
        for (; j + 8 <= rem; j += 8) {
            uint2 v[8];
#pragma unroll
            for (int u = 0; u < 8; u++) {
                int n = __shfl_sync(0xffffffffu, myidx, j + u);
                v[u] = xb[(size_t)n * 32 + lane];
            }
#pragma unroll
            for (int u = 0; u < 8; u++) {
                acc_word(v[u].x, a0);
                acc_word(v[u].y, a1);
            }
        }
        for (; j < rem; j++) {
            int n = __shfl_sync(0xffffffffu, myidx, j);
            uint2 v = xb[(size_t)n * 32 + lane];
            acc_word(v.x, a0);
            acc_word(v.y, a1);
        }
    }

    float inv = 1.0f / fmaxf((float)deg, 1.0f);
    float2 f0 = unpack_f32x2(a0), f1 = unpack_f32x2(a1);
    float4 r = make_float4(f0.x * inv, f0.y * inv, f1.x * inv, f1.y * inv);
    reinterpret_cast<float4*>(g_agg)[(size_t)node * 32 + lane] = r;
}

// ---------------------------------------------------------------------------
// Fused GEMM via portable mma.sync (tf32): out = [agg | x] @ WT_cat^T + b.
// CTA = 256 thr (8 warps), tile 128 rows x 128 cols, K=256 in 8 chunks of 32.
// Warp strip = 16 rows; 16 n-frags (m16n8k8), 64 fp32 accs per lane.
// smem padded to stride 36 -> conflict-free fragment LDS.
// ---------------------------------------------------------------------------
#define SMEM_STRIDE 36

__device__ __forceinline__ void mma_tf32(float* c, uint32_t a0, uint32_t a1,
                                         uint32_t a2, uint32_t a3,
                                         uint32_t b0, uint32_t b1) {
    asm volatile(
        "mma.sync.aligned.m16n8k8.row.col.f32.tf32.tf32.f32 "
        "{%0,%1,%2,%3}, {%4,%5,%6,%7}, {%8,%9}, {%0,%1,%2,%3};"
        : "+f"(c[0]), "+f"(c[1]), "+f"(c[2]), "+f"(c[3])
        : "r"(a0), "r"(a1), "r"(a2), "r"(a3), "r"(b0), "r"(b1));
}

__global__ void __launch_bounds__(256)
fused_gemm_kernel(const float* __restrict__ x,
                  const float* __restrict__ bias,
                  float* __restrict__ out) {
    __shared__ float sA[128][SMEM_STRIDE];   // 128 rows x 32 k (tf32 bits)
    __shared__ float sB[128][SMEM_STRIDE];   // 128 n    x 32 k (pre-rounded)

    int tid  = threadIdx.x;
    int w    = tid >> 5;        // warp 0..7 -> rows [16w, 16w+16)
    int lane = tid & 31;
    int g    = lane >> 2;       // groupID 0..7
    int tig  = lane & 3;        // thread-in-group 0..3
    int tile = blockIdx.x;

    float acc[16][4];
#pragma unroll
    for (int nf = 0; nf < 16; nf++)
#pragma unroll
        for (int q = 0; q < 4; q++) acc[nf][q] = 0.f;

    for (int ch = 0; ch < 8; ch++) {
        int k0 = ch * 32;
        // --- stage A chunk: 128 rows x 32 k, tf32-rounded ---
#pragma unroll
        for (int it = 0; it < 4; it++) {
            int idx = tid + 256 * it;         // 0..1023
            int row = idx >> 3;               // 0..127
            int j   = idx & 7;                // float4 index within 32 k
            int grow = tile * 128 + row;
            int arow = (grow < N_NODES) ? grow : (N_NODES - 1);
            const float* src = (k0 < 128)
                ? (g_agg + (size_t)arow * DIM + k0)
                : (x     + (size_t)arow * DIM + (k0 - 128));
            float4 v = *reinterpret_cast<const float4*>(src + j * 4);
            sA[row][j * 4 + 0] = __uint_as_float(tf32_rna(v.x));
            sA[row][j * 4 + 1] = __uint_as_float(tf32_rna(v.y));
            sA[row][j * 4 + 2] = __uint_as_float(tf32_rna(v.z));
            sA[row][j * 4 + 3] = __uint_as_float(tf32_rna(v.w));
        }
        // --- stage B chunk: 128 n x 32 k (already tf32) ---
#pragma unroll
        for (int it = 0; it < 4; it++) {
            int idx = tid + 256 * it;
            int n = idx >> 3;
            int j = idx & 7;
            float4 v = *reinterpret_cast<const float4*>(g_wt + (size_t)n * 256 + k0 + j * 4);
            *reinterpret_cast<float4*>(&sB[n][j * 4]) = v;
        }
        __syncthreads();

        // --- compute: 4 k8-steps x 16 n-frags ---
#pragma unroll
        for (int ks = 0; ks < 32; ks += 8) {
            uint32_t a0 = __float_as_uint(sA[16 * w + g][ks + tig]);
            uint32_t a1 = __float_as_uint(sA[16 * w + g + 8][ks + tig]);
            uint32_t a2 = __float_as_uint(sA[16 * w + g][ks + tig + 4]);
            uint32_t a3 = __float_as_uint(sA[16 * w + g + 8][ks + tig + 4]);
#pragma unroll
            for (int nf = 0; nf < 16; nf++) {
                uint32_t b0 = __float_as_uint(sB[8 * nf + g][ks + tig]);
                uint32_t b1 = __float_as_uint(sB[8 * nf + g][ks + tig + 4]);
                mma_tf32(acc[nf], a0, a1, a2, a3, b0, b1);
            }
        }
        __syncthreads();
    }

    // --- epilogue: c0/c1 at (row=g, col=2tig), c2/c3 at (row=g+8) ---
    int row0 = tile * 128 + 16 * w + g;
#pragma unroll
    for (int nf = 0; nf < 16; nf++) {
        int c = 8 * nf + 2 * tig;
        float2 bz = *reinterpret_cast<const float2*>(bias + c);
        if (row0 < N_NODES) {
            float2 o = make_float2(acc[nf][0] + bz.x, acc[nf][1] + bz.y);
            *reinterpret_cast<float2*>(out + (size_t)row0 * DIM + c) = o;
        }
        if (row0 + 8 < N_NODES) {
            float2 o = make_float2(acc[nf][2] + bz.x, acc[nf][3] + bz.y);
            *reinterpret_cast<float2*>(out + (size_t)(row0 + 8) * DIM + c) = o;
        }
    }
}

// ---------------------------------------------------------------------------
// Launch.
// s2:   convert(x->bf16) [eCvt] -> wt transpose [eWT]
// main: memset(cnt) -> fill -> [wait eCvt] gather -> [wait eWT] fused gemm
// ---------------------------------------------------------------------------
extern "C" void kernel_launch(void* const* d_in, const int* in_sizes, int n_in,
                              void* d_out, int out_size) {
    const float* x    = (const float*)d_in[0];
    const int*   ei32 = (const int*)d_in[1];
    const float* Wn   = (const float*)d_in[2];
    const float* Ws   = (const float*)d_in[3];
    const float* bias = (const float*)d_in[4];
    float* out = (float*)d_out;

    int n_edges = in_sizes[1] / 2;

    void* cnt_ptr = nullptr;
    cudaGetSymbolAddress(&cnt_ptr, g_cnt);

    cudaStream_t s2;
    cudaStreamCreateWithFlags(&s2, cudaStreamNonBlocking);
    cudaEvent_t eFork, eCvt, eWT;
    cudaEventCreateWithFlags(&eFork, cudaEventDisableTiming);
    cudaEventCreateWithFlags(&eCvt,  cudaEventDisableTiming);
    cudaEventCreateWithFlags(&eWT,   cudaEventDisableTiming);

    cudaEventRecord(eFork, 0);
    cudaStreamWaitEvent(s2, eFork, 0);

    int n4 = N_NODES * (DIM / 4);
    convert_kernel<<<(n4 + 255) / 256, 256, 0, s2>>>(x);
    cudaEventRecord(eCvt, s2);
    wt_kernel<<<128, 256, 0, s2>>>(Wn, Ws);
    cudaEventRecord(eWT, s2);

    cudaMemsetAsync(cnt_ptr, 0, (size_t)N_NODES * sizeof(int));
    fill_kernel<<<(n_edges + 255) / 256, 256>>>(ei32, n_edges);

    cudaStreamWaitEvent(0, eCvt, 0);
    gather_kernel<<<(N_NODES * 32 + 255) / 256, 256>>>();

    cudaStreamWaitEvent(0, eWT, 0);
    fused_gemm_kernel<<<NTILES, 256>>>(x, bias, out);

    // Handles intentionally not destroyed mid-capture (host-side only).
}

// round 10
// speedup vs baseline: 1.6867x; 1.0945x over previous
#include <cuda_runtime.h>
#include <cuda_bf16.h>
#include <cstdint>

#define N_NODES 50000
#define DIM 128
#define CAP 160                        // bucket slots/node (Poisson(64): P(>160)~1e-24)
#define NTILES ((N_NODES + 127) / 128) // 391

// Scratch (__device__ globals per allocation rules)
__device__ __align__(16) float g_agg[(size_t)N_NODES * DIM];        // agg_mean fp32
__device__ __align__(16) __nv_bfloat16 g_xb[(size_t)N_NODES * DIM]; // x in bf16
__device__ int g_cnt[N_NODES];               // cursor during fill == degree after
__device__ int g_bkt[(size_t)N_NODES * CAP]; // bucketed adjacency (both directions)
__device__ __align__(16) float g_wt[128 * 256]; // WT_cat[n][k] = W*[k][n], tf32-rounded

__device__ __forceinline__ uint32_t tf32_rna(float f) {
    uint32_t r;
    asm("cvt.rna.tf32.f32 %0, %1;" : "=r"(r) : "f"(f));
    return r;
}

// ---------------------------------------------------------------------------
// Convert x -> bf16 scratch (forked stream).
// ---------------------------------------------------------------------------
__global__ void __launch_bounds__(256)
convert_kernel(const float* __restrict__ x) {
    int i = blockIdx.x * blockDim.x + threadIdx.x;
    if (i >= N_NODES * (DIM / 4)) return;
    float4 v = reinterpret_cast<const float4*>(x)[i];
    __nv_bfloat162 lo = __float22bfloat162_rn(make_float2(v.x, v.y));
    __nv_bfloat162 hi = __float22bfloat162_rn(make_float2(v.z, v.w));
    uint2 o;
    o.x = *reinterpret_cast<uint32_t*>(&lo);
    o.y = *reinterpret_cast<uint32_t*>(&hi);
    reinterpret_cast<uint2*>(g_xb)[i] = o;
}

// ---------------------------------------------------------------------------
// Build WT_cat[n][k] = (k<128 ? Wn[k][n] : Ws[k-128][n]), tf32-rounded.
// ---------------------------------------------------------------------------
__global__ void __launch_bounds__(256)
wt_kernel(const float* __restrict__ Wn, const float* __restrict__ Ws) {
    int idx = blockIdx.x * 256 + threadIdx.x;   // 32768 total
    if (idx >= 128 * 256) return;
    int k = idx >> 7;        // 0..255
    int n = idx & 127;       // coalesced read within a W row
    float v = (k < 128) ? Wn[k * 128 + n] : Ws[(k - 128) * 128 + n];
    g_wt[n * 256 + k] = __uint_as_float(tf32_rna(v));
}

// ---------------------------------------------------------------------------
// Bucket fill with inline dtype detect (int64 indices -> odd words all zero).
// At the L1tex scattered-write floor (~48us): 2 ATOMG + 2 STG per edge.
// ---------------------------------------------------------------------------
__device__ __forceinline__ void insert_edge(int s, int d) {
    if ((unsigned)s >= N_NODES || (unsigned)d >= N_NODES) return;
    int ps = atomicAdd(&g_cnt[s], 1);
    if (ps < CAP) g_bkt[(size_t)s * CAP + ps] = d;
    int pd = atomicAdd(&g_cnt[d], 1);
    if (pd < CAP) g_bkt[(size_t)d * CAP + pd] = s;
}

__global__ void __launch_bounds__(256)
fill_kernel(const int* __restrict__ ei32, int n_edges) {
    bool is64 = ((ei32[1] | ei32[3] | ei32[5] | ei32[7]) == 0);  // L1 broadcast
    int e = blockIdx.x * blockDim.x + threadIdx.x;
    if (is64) {
        if (e >= n_edges) return;
        int4 q = reinterpret_cast<const int4*>(ei32)[e];
        insert_edge(q.x, q.z);
    } else {
        int e0 = 2 * e;
        if (e0 >= n_edges) return;
        int4 q = reinterpret_cast<const int4*>(ei32)[e];
        insert_edge(q.x, q.y);
        if (e0 + 1 < n_edges) insert_edge(q.z, q.w);
    }
}

// ---------------------------------------------------------------------------
// Gather-sum v5: R5 shape (1 node/warp, uint2/lane, 8-deep MLP) + pairwise
// bf16 pre-sum (HADD2) to halve the fp32-convert ALU work (issue-bound fix).
// ---------------------------------------------------------------------------
__device__ __forceinline__ void acc_word(uint32_t w, unsigned long long& acc) {
    uint32_t lo = w << 16;
    uint32_t hi = w & 0xFFFF0000u;
    unsigned long long p;
    asm("mov.b64 %0, {%1, %2};" : "=l"(p) : "r"(lo), "r"(hi));
    asm("add.rn.f32x2 %0, %0, %1;" : "+l"(acc) : "l"(p));
}
__device__ __forceinline__ uint32_t hadd2_bits(uint32_t a, uint32_t b) {
    __nv_bfloat162 x = *reinterpret_cast<__nv_bfloat162*>(&a);
    __nv_bfloat162 y = *reinterpret_cast<__nv_bfloat162*>(&b);
    __nv_bfloat162 r = __hadd2(x, y);
    return *reinterpret_cast<uint32_t*>(&r);
}
__device__ __forceinline__ float2 unpack_f32x2(unsigned long long v) {
    uint32_t lo, hi;
    asm("mov.b64 {%0, %1}, %2;" : "=r"(lo), "=r"(hi) : "l"(v));
    return make_float2(__uint_as_float(lo), __uint_as_float(hi));
}

__global__ void __launch_bounds__(256)
gather_kernel() {
    int node = (blockIdx.x * blockDim.x + threadIdx.x) >> 5;
    int lane = threadIdx.x & 31;
    if (node >= N_NODES) return;

    int deg = g_cnt[node];
    int m = (deg < CAP) ? deg : CAP;

    const uint2* __restrict__ xb  = reinterpret_cast<const uint2*>(g_xb);
    const int*   __restrict__ bkt = g_bkt + (size_t)node * CAP;

    unsigned long long a0 = 0ull, a1 = 0ull;

    int i = 0;
    for (; i + 32 <= m; i += 32) {
        int myidx = bkt[i + lane];
#pragma unroll
        for (int h = 0; h < 4; h++) {
            uint2 v[8];
#pragma unroll
            for (int u = 0; u < 8; u++) {
                int n = __shfl_sync(0xffffffffu, myidx, h * 8 + u);
                v[u] = xb[(size_t)n * 32 + lane];
            }
#pragma unroll
            for (int p = 0; p < 4; p++) {   // merge neighbor pairs in bf16
                uint32_t mx = hadd2_bits(v[2 * p].x, v[2 * p + 1].x);
                uint32_t my = hadd2_bits(v[2 * p].y, v[2 * p + 1].y);
                acc_word(mx, a0);
                acc_word(my, a1);
            }
        }
    }
    int rem = m - i;
    if (rem > 0) {
        int myidx = (lane < rem) ? bkt[i + lane] : 0;
        int j = 0;
        for (; j + 2 <= rem; j += 2) {
            int n0 = __shfl_sync(0xffffffffu, myidx, j);
            int n1 = __shfl_sync(0xffffffffu, myidx, j + 1);
            uint2 v0 = xb[(size_t)n0 * 32 + lane];
            uint2 v1 = xb[(size_t)n1 * 32 + lane];
            acc_word(hadd2_bits(v0.x, v1.x), a0);
            acc_word(hadd2_bits(v0.y, v1.y), a1);
        }
        if (j < rem) {
            int n = __shfl_sync(0xffffffffu, myidx, j);
            uint2 v = xb[(size_t)n * 32 + lane];
            acc_word(v.x, a0);
            acc_word(v.y, a1);
        }
    }

    float inv = 1.0f / fmaxf((float)deg, 1.0f);
    float2 f0 = unpack_f32x2(a0), f1 = unpack_f32x2(a1);
    float4 r = make_float4(f0.x * inv, f0.y * inv, f1.x * inv, f1.y * inv);
    reinterpret_cast<float4*>(g_agg)[(size_t)node * 32 + lane] = r;
}

// ---------------------------------------------------------------------------
// Fused GEMM via mma.sync tf32: out = [agg | x] @ WT_cat^T + b.
// CTA = 256 thr (8 warps), tile 128x128, K=256 in 8 smem chunks of 32.
// Warp tile 32 rows x 64 cols (2 m-frags x 8 n-frags): 24 LDS / k8-step.
// ---------------------------------------------------------------------------
#define SMEM_STRIDE 36

__device__ __forceinline__ void mma_tf32(float* c, uint32_t a0, uint32_t a1,
                                         uint32_t a2, uint32_t a3,
                                         uint32_t b0, uint32_t b1) {
    asm volatile(
        "mma.sync.aligned.m16n8k8.row.col.f32.tf32.tf32.f32 "
        "{%0,%1,%2,%3}, {%4,%5,%6,%7}, {%8,%9}, {%0,%1,%2,%3};"
        : "+f"(c[0]), "+f"(c[1]), "+f"(c[2]), "+f"(c[3])
        : "r"(a0), "r"(a1), "r"(a2), "r"(a3), "r"(b0), "r"(b1));
}

__global__ void __launch_bounds__(256)
fused_gemm_kernel(const float* __restrict__ x,
                  const float* __restrict__ bias,
                  float* __restrict__ out) {
    __shared__ float sA[128][SMEM_STRIDE];   // 128 rows x 32 k (tf32 bits)
    __shared__ float sB[128][SMEM_STRIDE];   // 128 n    x 32 k (pre-rounded)

    int tid  = threadIdx.x;
    int w    = tid >> 5;
    int lane = tid & 31;
    int g    = lane >> 2;       // groupID 0..7
    int tig  = lane & 3;        // thread-in-group 0..3
    int tile = blockIdx.x;

    int wr = (w & 3) * 32;      // warp row base
    int wc = (w >> 2) * 64;     // warp col base

    float acc[2][8][4];
#pragma unroll
    for (int mi = 0; mi < 2; mi++)
#pragma unroll
        for (int nf = 0; nf < 8; nf++)
#pragma unroll
            for (int q = 0; q < 4; q++) acc[mi][nf][q] = 0.f;

    for (int ch = 0; ch < 8; ch++) {
        int k0 = ch * 32;
        // --- stage A chunk: 128 rows x 32 k, tf32-rounded ---
#pragma unroll
        for (int it = 0; it < 4; it++) {
            int idx = tid + 256 * it;         // 0..1023
            int row = idx >> 3;
            int j   = idx & 7;
            int grow = tile * 128 + row;
            int arow = (grow < N_NODES) ? grow : (N_NODES - 1);
            const float* src = (k0 < 128)
                ? (g_agg + (size_t)arow * DIM + k0)
                : (x     + (size_t)arow * DIM + (k0 - 128));
            float4 v = *reinterpret_cast<const float4*>(src + j * 4);
            sA[row][j * 4 + 0] = __uint_as_float(tf32_rna(v.x));
            sA[row][j * 4 + 1] = __uint_as_float(tf32_rna(v.y));
            sA[row][j * 4 + 2] = __uint_as_float(tf32_rna(v.z));
            sA[row][j * 4 + 3] = __uint_as_float(tf32_rna(v.w));
        }
        // --- stage B chunk: 128 n x 32 k (already tf32) ---
#pragma unroll
        for (int it = 0; it < 4; it++) {
            int idx = tid + 256 * it;
            int n = idx >> 3;
            int j = idx & 7;
            float4 v = *reinterpret_cast<const float4*>(g_wt + (size_t)n * 256 + k0 + j * 4);
            *reinterpret_cast<float4*>(&sB[n][j * 4]) = v;
        }
        __syncthreads();

        // --- compute: 4 k8-steps, 2 m-frags x 8 n-frags ---
#pragma unroll
        for (int ks = 0; ks < 32; ks += 8) {
            uint32_t a[2][4];
#pragma unroll
            for (int mi = 0; mi < 2; mi++) {
                int r = wr + 16 * mi + g;
                a[mi][0] = __float_as_uint(sA[r][ks + tig]);
                a[mi][1] = __float_as_uint(sA[r + 8][ks + tig]);
                a[mi][2] = __float_as_uint(sA[r][ks + tig + 4]);
                a[mi][3] = __float_as_uint(sA[r + 8][ks + tig + 4]);
            }
#pragma unroll
            for (int nf = 0; nf < 8; nf++) {
                int n = wc + 8 * nf + g;
                uint32_t b0 = __float_as_uint(sB[n][ks + tig]);
                uint32_t b1 = __float_as_uint(sB[n][ks + tig + 4]);
                mma_tf32(acc[0][nf], a[0][0], a[0][1], a[0][2], a[0][3], b0, b1);
                mma_tf32(acc[1][nf], a[1][0], a[1][1], a[1][2], a[1][3], b0, b1);
            }
        }
        __syncthreads();
    }

    // --- epilogue: c0/c1 at (row g, col 2tig), c2/c3 at row g+8 ---
#pragma unroll
    for (int mi = 0; mi < 2; mi++) {
        int row0 = tile * 128 + wr + 16 * mi + g;
#pragma unroll
        for (int nf = 0; nf < 8; nf++) {
            int c = wc + 8 * nf + 2 * tig;
            float2 bz = *reinterpret_cast<const float2*>(bias + c);
            if (row0 < N_NODES) {
                float2 o = make_float2(acc[mi][nf][0] + bz.x, acc[mi][nf][1] + bz.y);
                *reinterpret_cast<float2*>(out + (size_t)row0 * DIM + c) = o;
            }
            if (row0 + 8 < N_NODES) {
                float2 o = make_float2(acc[mi][nf][2] + bz.x, acc[mi][nf][3] + bz.y);
                *reinterpret_cast<float2*>(out + (size_t)(row0 + 8) * DIM + c) = o;
            }
        }
    }
}

// ---------------------------------------------------------------------------
// Launch.
// s2:   convert(x->bf16) [eCvt] -> wt transpose [eWT]
// main: memset(cnt) -> fill -> [wait eCvt] gather -> [wait eWT] fused gemm
// ---------------------------------------------------------------------------
extern "C" void kernel_launch(void* const* d_in, const int* in_sizes, int n_in,
                              void* d_out, int out_size) {
    const float* x    = (const float*)d_in[0];
    const int*   ei32 = (const int*)d_in[1];
    const float* Wn   = (const float*)d_in[2];
    const float* Ws   = (const float*)d_in[3];
    const float* bias = (const float*)d_in[4];
    float* out = (float*)d_out;

    int n_edges = in_sizes[1] / 2;

    void* cnt_ptr = nullptr;
    cudaGetSymbolAddress(&cnt_ptr, g_cnt);

    cudaStream_t s2;
    cudaStreamCreateWithFlags(&s2, cudaStreamNonBlocking);
    cudaEvent_t eFork, eCvt, eWT;
    cudaEventCreateWithFlags(&eFork, cudaEventDisableTiming);
    cudaEventCreateWithFlags(&eCvt,  cudaEventDisableTiming);
    cudaEventCreateWithFlags(&eWT,   cudaEventDisableTiming);

    cudaEventRecord(eFork, 0);
    cudaStreamWaitEvent(s2, eFork, 0);

    int n4 = N_NODES * (DIM / 4);
    convert_kernel<<<(n4 + 255) / 256, 256, 0, s2>>>(x);
    cudaEventRecord(eCvt, s2);
    wt_kernel<<<128, 256, 0, s2>>>(Wn, Ws);
    cudaEventRecord(eWT, s2);

    cudaMemsetAsync(cnt_ptr, 0, (size_t)N_NODES * sizeof(int));
    fill_kernel<<<(n_edges + 255) / 256, 256>>>(ei32, n_edges);

    cudaStreamWaitEvent(0, eCvt, 0);
    gather_kernel<<<(N_NODES * 32 + 255) / 256, 256>>>();

    cudaStreamWaitEvent(0, eWT, 0);
    fused_gemm_kernel<<<NTILES, 256>>>(x, bias, out);

    // Handles intentionally not destroyed mid-capture (host-side only).
}